// round 12
// baseline (speedup 1.0000x reference)
#include <cuda_runtime.h>
#include <cuda_bf16.h>
#include <cuda_fp16.h>
#include <cstdint>

#define N_NODES 100000
#define N_EDGES 1600000
#define EMB 64
#define HID 128
#define N_GRAPHS 512
#define N_TASKS 128
#define FULLMASK 0xffffffffu
#define NB_SCAN 98   // ceil(100000/1024)

// ---------------- device scratch (static, no allocation) ----------------
__device__ __align__(16) uint4 g_x0h[N_NODES * 8];     // 64 halves per node
__device__ __align__(16) uint4 g_agg0h[N_NODES * 8];   // = x0 + sum(msg) after agg0
__device__ __align__(16) uint4 g_x1h[N_NODES * 16];    // 128 halves per node
__device__ __align__(16) uint4 g_agg1h[N_NODES * 16];  // = x1 + sum(msg) after agg1
__device__ __align__(16) uint4 g_t0h[16 * 8];          // bond table L0 (fp16)
__device__ __align__(16) uint4 g_t1h[16 * 16];         // bond table L1 (fp16)
__device__ __align__(16) float g_pool[N_GRAPHS * HID];
// fp16 weights, pre-swizzled: layer0 [W1 16384 | W2 32768], layer1 [W1 32768 | W2 32768]
__device__ __align__(16) unsigned char g_wb0[49152];
__device__ __align__(16) unsigned char g_wb1[65536];
// CSR (built once per launch, shared by both layers)
__device__ int g_deg[N_NODES];
__device__ int g_off[N_NODES + 1];
__device__ int g_cur[N_NODES];
__device__ int g_bsum[NB_SCAN];
__device__ uint32_t g_csr[N_EDGES];    // src | (bt << 17)

// ---------------- helpers ----------------
__device__ __forceinline__ void red_add_v2(float* p, float a, float b) {
    asm volatile("red.global.add.v2.f32 [%0], {%1,%2};"
                 :: "l"(p), "f"(a), "f"(b) : "memory");
}
__device__ __forceinline__ void cp16(uint32_t dst, const void* src, bool valid) {
    if (valid)
        asm volatile("cp.async.cg.shared.global [%0], [%1], 16;" :: "r"(dst), "l"(src) : "memory");
    else
        asm volatile("cp.async.cg.shared.global [%0], [%1], 16, 0;" :: "r"(dst), "l"(src) : "memory");
}
__device__ __forceinline__ float elu_fast(float x) { return x > 0.f ? x : (__expf(x) - 1.f); }
__device__ __forceinline__ uint32_t smem_u32(const void* p) {
    uint32_t a;
    asm("{ .reg .u64 t; cvta.to.shared.u64 t, %1; cvt.u32.u64 %0, t; }" : "=r"(a) : "l"(p));
    return a;
}
// half2 relu(a+b)
__device__ __forceinline__ uint32_t h2ra(uint32_t a, uint32_t b) {
    __half2 s = __hadd2(*(__half2*)&a, *(__half2*)&b);
    __half2 z = __float2half2_rn(0.f);
    s = __hmax2(s, z);
    return *(uint32_t*)&s;
}
__device__ __forceinline__ uint32_t h2a(uint32_t a, uint32_t b) {
    __half2 s = __hadd2(*(__half2*)&a, *(__half2*)&b);
    return *(uint32_t*)&s;
}
__device__ __forceinline__ uint4 msg4(uint4 v, uint4 t) {
    uint4 m;
    m.x = h2ra(v.x, t.x); m.y = h2ra(v.y, t.y);
    m.z = h2ra(v.z, t.z); m.w = h2ra(v.w, t.w);
    return m;
}
__device__ __forceinline__ uint4 hadd2x4(uint4 a, uint4 b) {
    uint4 o;
    o.x = h2a(a.x, b.x); o.y = h2a(a.y, b.y);
    o.z = h2a(a.z, b.z); o.w = h2a(a.w, b.w);
    return o;
}
__device__ __forceinline__ uint4 shfl_xor4(uint4 a, int m) {
    uint4 o;
    o.x = __shfl_xor_sync(FULLMASK, a.x, m);
    o.y = __shfl_xor_sync(FULLMASK, a.y, m);
    o.z = __shfl_xor_sync(FULLMASK, a.z, m);
    o.w = __shfl_xor_sync(FULLMASK, a.w, m);
    return o;
}
__device__ __forceinline__ uint32_t packh2(float a, float b) {
    __half2 h = __floats2half2_rn(a, b);
    return *(uint32_t*)&h;
}
// swizzled byte offset within a [row][col] 16-bit-element tile; rowb bytes per row.
__device__ __forceinline__ uint32_t swz(int r, int c, int rowb) {
    return (uint32_t)(r * rowb + ((((c >> 3) ^ (r & 7))) << 4) + (c & 7) * 2);
}
__device__ __forceinline__ void ldsm_x4(uint32_t a[4], uint32_t addr) {
    asm volatile("ldmatrix.sync.aligned.m8n8.x4.shared.b16 {%0,%1,%2,%3}, [%4];"
                 : "=r"(a[0]), "=r"(a[1]), "=r"(a[2]), "=r"(a[3]) : "r"(addr));
}
__device__ __forceinline__ void ldsm_x4_t(uint32_t a[4], uint32_t addr) {
    asm volatile("ldmatrix.sync.aligned.m8n8.x4.trans.shared.b16 {%0,%1,%2,%3}, [%4];"
                 : "=r"(a[0]), "=r"(a[1]), "=r"(a[2]), "=r"(a[3]) : "r"(addr));
}
__device__ __forceinline__ void mma_fp16(float d[4], const uint32_t a[4], uint32_t b0, uint32_t b1) {
    asm volatile("mma.sync.aligned.m16n8k16.row.col.f32.f16.f16.f32 "
                 "{%0,%1,%2,%3}, {%4,%5,%6,%7}, {%8,%9}, {%0,%1,%2,%3};"
                 : "+f"(d[0]), "+f"(d[1]), "+f"(d[2]), "+f"(d[3])
                 : "r"(a[0]), "r"(a[1]), "r"(a[2]), "r"(a[3]), "r"(b0), "r"(b1));
}

// ---------------- prep: pool/deg zero + fp16 bond tables + weight blobs + gather ----
__global__ void k_prep(const float* __restrict__ bond_emb,
                       const float* __restrict__ we0, const float* __restrict__ be0,
                       const float* __restrict__ we1, const float* __restrict__ be1,
                       const float* __restrict__ w1_0, const float* __restrict__ w2_0,
                       const float* __restrict__ w1_1, const float* __restrict__ w2_1,
                       const int* __restrict__ x_idx, const float* __restrict__ atom_emb) {
    int tid = blockIdx.x * blockDim.x + threadIdx.x;
    int nth = gridDim.x * blockDim.x;
    for (int i = tid; i < N_GRAPHS * HID; i += nth) g_pool[i] = 0.f;
    for (int i = tid; i < N_NODES; i += nth) g_deg[i] = 0;
    for (int i = tid; i < 16 * EMB; i += nth) {
        int bt = i >> 6, o = i & 63;
        float acc = be0[o];
        #pragma unroll 8
        for (int k = 0; k < EMB; k++) acc += bond_emb[bt * EMB + k] * we0[k * EMB + o];
        ((__half*)g_t0h)[i] = __float2half_rn(acc);
    }
    for (int i = tid; i < 16 * HID; i += nth) {
        int bt = i >> 7, o = i & 127;
        float acc = be1[o];
        #pragma unroll 8
        for (int k = 0; k < EMB; k++) acc += bond_emb[bt * EMB + k] * we1[k * HID + o];
        ((__half*)g_t1h)[i] = __float2half_rn(acc);
    }
    for (int i = tid; i < 64 * 128; i += nth) {          // L0 W1
        int k = i >> 7, n = i & 127;
        *(__half*)(g_wb0 + swz(k, n, 256)) = __float2half_rn(w1_0[i]);
    }
    for (int i = tid; i < 128 * 128; i += nth) {         // L0 W2
        int k = i >> 7, n = i & 127;
        *(__half*)(g_wb0 + 16384 + swz(k, n, 256)) = __float2half_rn(w2_0[i]);
    }
    for (int i = tid; i < 128 * 128; i += nth) {         // L1 W1
        int k = i >> 7, n = i & 127;
        *(__half*)(g_wb1 + swz(k, n, 256)) = __float2half_rn(w1_1[i]);
    }
    for (int i = tid; i < 128 * 128; i += nth) {         // L1 W2
        int k = i >> 7, n = i & 127;
        *(__half*)(g_wb1 + 32768 + swz(k, n, 256)) = __float2half_rn(w2_1[i]);
    }
    // gather atom embeddings (fp32 -> fp16)
    const float4* ae = (const float4*)atom_emb;
    uint2* x0 = (uint2*)g_x0h;
    const int NITEMS = N_NODES * 16;
    for (int i = tid; i < NITEMS; i += nth) {
        int node = i >> 4;
        int c = i & 15;
        int a = x_idx[node];
        float4 v = ae[a * 16 + c];
        uint2 o;
        o.x = packh2(v.x, v.y); o.y = packh2(v.z, v.w);
        x0[i] = o;
    }
}

// ---------------- CSR build (R9-proven code) ----------------
__global__ void k_hist(const int* __restrict__ ei) {
    int tid = blockIdx.x * blockDim.x + threadIdx.x;
    int nth = gridDim.x * blockDim.x;
    for (int e = tid; e < N_EDGES; e += nth)
        atomicAdd(&g_deg[ei[N_EDGES + e]], 1);
}

__global__ void k_scan1() {
    __shared__ int s[1024];
    int i = blockIdx.x * 1024 + threadIdx.x;
    int v = (i < N_NODES) ? g_deg[i] : 0;
    s[threadIdx.x] = v;
    __syncthreads();
    #pragma unroll
    for (int d = 1; d < 1024; d <<= 1) {
        int t = (threadIdx.x >= d) ? s[threadIdx.x - d] : 0;
        __syncthreads();
        s[threadIdx.x] += t;
        __syncthreads();
    }
    if (i < N_NODES) g_off[i] = s[threadIdx.x] - v;   // exclusive
    if (threadIdx.x == 1023) g_bsum[blockIdx.x] = s[1023];
}

__global__ void k_scan2() {
    __shared__ int bs[NB_SCAN];
    if (threadIdx.x < NB_SCAN) bs[threadIdx.x] = g_bsum[threadIdx.x];
    __syncthreads();
    int add = 0;
    for (int b = 0; b < (int)blockIdx.x; b++) add += bs[b];
    int i = blockIdx.x * 1024 + threadIdx.x;
    if (i < N_NODES) {
        int o = g_off[i] + add;
        g_off[i] = o;
        g_cur[i] = o;
    }
    if (blockIdx.x == NB_SCAN - 1 && threadIdx.x == 0)
        g_off[N_NODES] = add + bs[NB_SCAN - 1];
}

__global__ void k_scatter(const int* __restrict__ ei, const int* __restrict__ ea) {
    int tid = blockIdx.x * blockDim.x + threadIdx.x;
    int nth = gridDim.x * blockDim.x;
    for (int e = tid; e < N_EDGES; e += nth) {
        int d = ei[N_EDGES + e];
        uint32_t rec = (uint32_t)ei[e] | ((uint32_t)ea[e] << 17);
        int pos = atomicAdd(&g_cur[d], 1);
        g_csr[pos] = rec;
    }
}

// ---------------- agg layer 0: warp per node, 4 edge-slots x 8 chunks ----------------
// Key vs R9: recs preloaded in ONE coalesced LDG then shfl-broadcast — no
// pointer-chase in the gather loop; unrolled independent gathers (MLP~4).
__global__ void k_agg0() {
    __shared__ uint4 t0s[16 * 8];
    for (int i = threadIdx.x; i < 16 * 8; i += blockDim.x) t0s[i] = g_t0h[i];
    __syncthreads();
    int lane = threadIdx.x & 31;
    int wid = (blockIdx.x * blockDim.x + threadIdx.x) >> 5;
    int nw = (gridDim.x * blockDim.x) >> 5;
    int e = lane >> 3, c = lane & 7;
    for (int n = wid; n < N_NODES; n += nw) {
        int beg = g_off[n];
        int deg = g_off[n + 1] - beg;
        uint4 acc = (e == 0) ? g_x0h[n * 8 + c] : make_uint4(0u, 0u, 0u, 0u);  // pre-bias x
        for (int base = 0; base < deg; base += 32) {
            int nrec = min(32, deg - base);
            uint32_t rec = 0u;
            if (base + lane < deg) rec = g_csr[beg + base + lane];
            #pragma unroll 4
            for (int j = 0; j < nrec; j += 4) {
                int idx = j + e;
                uint32_t r = __shfl_sync(FULLMASK, rec, idx & 31);
                if (idx < nrec) {
                    int src = r & 0x1FFFF;
                    int bt  = r >> 17;
                    uint4 v = g_x0h[src * 8 + c];
                    uint4 t = t0s[bt * 8 + c];
                    acc = hadd2x4(acc, msg4(v, t));
                }
            }
        }
        acc = hadd2x4(acc, shfl_xor4(acc, 8));
        acc = hadd2x4(acc, shfl_xor4(acc, 16));
        if (lane < 8) g_agg0h[n * 8 + c] = acc;
    }
}

// ---------------- agg layer 1: warp per node, 2 edge-slots x 16 chunks ----------------
__global__ void k_agg1() {
    __shared__ uint4 t1s[16 * 16];
    for (int i = threadIdx.x; i < 16 * 16; i += blockDim.x) t1s[i] = g_t1h[i];
    __syncthreads();
    int lane = threadIdx.x & 31;
    int wid = (blockIdx.x * blockDim.x + threadIdx.x) >> 5;
    int nw = (gridDim.x * blockDim.x) >> 5;
    int e = lane >> 4, c = lane & 15;
    for (int n = wid; n < N_NODES; n += nw) {
        int beg = g_off[n];
        int deg = g_off[n + 1] - beg;
        uint4 acc = (e == 0) ? g_x1h[n * 16 + c] : make_uint4(0u, 0u, 0u, 0u); // pre-bias x
        for (int base = 0; base < deg; base += 32) {
            int nrec = min(32, deg - base);
            uint32_t rec = 0u;
            if (base + lane < deg) rec = g_csr[beg + base + lane];
            #pragma unroll 4
            for (int j = 0; j < nrec; j += 2) {
                int idx = j + e;
                uint32_t r = __shfl_sync(FULLMASK, rec, idx & 31);
                if (idx < nrec) {
                    int src = r & 0x1FFFF;
                    int bt  = r >> 17;
                    uint4 v = g_x1h[src * 16 + c];
                    uint4 t = t1s[bt * 16 + c];
                    acc = hadd2x4(acc, msg4(v, t));
                }
            }
        }
        acc = hadd2x4(acc, shfl_xor4(acc, 16));
        if (lane < 16) g_agg1h[n * 16 + c] = acc;
    }
}

// ============ GINE MLP: cp.async-pipelined HMMA fp16 (R11-proven) ============
template<int K1, bool L1>
__global__ void __launch_bounds__(1024, 1)
k_mlp_cp(const float* __restrict__ b1, const float* __restrict__ b2,
         const int* __restrict__ batch) {
    extern __shared__ char smem[];
    constexpr int W1B = K1 * 256;
    constexpr int W2B = 32768;
    constexpr int RB  = K1 * 2;            // bytes per As row
    constexpr int ASB = 128 * RB;
    constexpr int CPR = RB / 16;           // 16B chunks per row (8 or 16)
    char* W1s  = smem;
    char* W2s  = smem + W1B;
    char* Asb  = smem + W1B + W2B;
    char* As2b = Asb + ASB;
    float* b1s = (float*)(As2b + 32768);
    float* b2s = b1s + 128;

    const char* ag = (const char*)(L1 ? g_agg1h : g_agg0h);
    const unsigned char* blob = L1 ? g_wb1 : g_wb0;

    int tid = threadIdx.x;
    {
        const uint4* src = (const uint4*)blob;
        uint4* dst = (uint4*)smem;
        for (int i = tid; i < (W1B + W2B) / 16; i += 1024) dst[i] = src[i];
    }
    if (tid < 128) { b1s[tid] = b1[tid]; b2s[tid] = b2[tid]; }

    uint32_t As_u  = smem_u32(Asb);
    uint32_t As2_u = smem_u32(As2b);
    uint32_t W1_u  = smem_u32(W1s);
    uint32_t W2_u  = smem_u32(W2s);

    int lane = tid & 31, wq = tid >> 5;
    int mbase = (wq & 7) * 16;
    int nbase = (wq >> 3) * 32;
    int g = lane >> 3, lr = lane & 7;
    int fr = (g & 1) * 8 + lr;
    int fc8 = (g >> 1) * 8;
    int qr = lane >> 2, qp = lane & 3;

    const int NT = (N_NODES + 127) / 128;  // 782

    auto prefetch = [&](int T) {
        #pragma unroll
        for (int v = 0; v < (128 * CPR) / 1024; v++) {
            int idx = v * 1024 + tid;
            int r = idx / CPR, c = idx % CPR;
            int node = T * 128 + r;
            uint32_t dst = As_u + r * RB + (uint32_t)((c ^ (r & 7)) << 4);
            bool valid = node < N_NODES;
            const char* src = valid ? ag + ((size_t)node * RB + c * 16) : ag;
            cp16(dst, src, valid);
        }
        asm volatile("cp.async.commit_group;" ::: "memory");
    };

    if ((int)blockIdx.x < NT) prefetch(blockIdx.x);

    for (int tile = blockIdx.x; tile < NT; tile += gridDim.x) {
        asm volatile("cp.async.wait_group 0;" ::: "memory");
        __syncthreads();   // As (and first-pass weights) visible to all

        float d0[4][4];
        #pragma unroll
        for (int i = 0; i < 4; i++)
            #pragma unroll
            for (int j = 0; j < 4; j++) d0[i][j] = 0.f;

        // ---- GEMM1: A[128xK1] @ W1 ----
        #pragma unroll
        for (int ks = 0; ks < K1 / 16; ks++) {
            uint32_t a0[4];
            ldsm_x4(a0, As_u + swz(mbase + fr, ks * 16 + fc8, RB));
            #pragma unroll
            for (int np = 0; np < 2; np++) {
                uint32_t bh[4];
                ldsm_x4_t(bh, W1_u + swz(ks * 16 + fr, nbase + np * 16 + fc8, 256));
                mma_fp16(d0[2 * np], a0, bh[0], bh[1]);
                mma_fp16(d0[2 * np + 1], a0, bh[2], bh[3]);
            }
        }

        // ---- epilogue1: t = elu(D + b1) -> As2 (fp16, swizzled) ----
        #pragma unroll
        for (int i = 0; i < 4; i++) {
            int n = nbase + i * 8 + qp * 2;
            float bb0 = b1s[n], bb1 = b1s[n + 1];
            *(uint32_t*)(As2b + swz(mbase + qr,     n, 256)) = packh2(elu_fast(d0[i][0] + bb0), elu_fast(d0[i][1] + bb1));
            *(uint32_t*)(As2b + swz(mbase + qr + 8, n, 256)) = packh2(elu_fast(d0[i][2] + bb0), elu_fast(d0[i][3] + bb1));
        }
        __syncthreads();   // As2 ready; all GEMM1 reads of As done

        // ---- prefetch next tile into As (overlaps GEMM2 + epilogue2) ----
        int nxt = tile + gridDim.x;
        if (nxt < NT) prefetch(nxt);

        #pragma unroll
        for (int i = 0; i < 4; i++)
            #pragma unroll
            for (int j = 0; j < 4; j++) d0[i][j] = 0.f;

        // ---- GEMM2: t[128x128] @ W2 ----
        #pragma unroll
        for (int ks = 0; ks < 8; ks++) {
            uint32_t a0[4];
            ldsm_x4(a0, As2_u + swz(mbase + fr, ks * 16 + fc8, 256));
            #pragma unroll
            for (int np = 0; np < 2; np++) {
                uint32_t bh[4];
                ldsm_x4_t(bh, W2_u + swz(ks * 16 + fr, nbase + np * 16 + fc8, 256));
                mma_fp16(d0[2 * np], a0, bh[0], bh[1]);
                mma_fp16(d0[2 * np + 1], a0, bh[2], bh[3]);
            }
        }

        // ---- epilogue2 ----
        if constexpr (!L1) {
            #pragma unroll
            for (int f = 0; f < 2; f++) {
                int row = mbase + qr + f * 8;
                int node = tile * 128 + row;
                if (node < N_NODES) {
                    uint32_t* xo = (uint32_t*)g_x1h + (size_t)node * 64;
                    #pragma unroll
                    for (int i = 0; i < 4; i++) {
                        int n = nbase + i * 8 + qp * 2;
                        float o0 = elu_fast(d0[i][2 * f]     + b2s[n]);
                        float o1 = elu_fast(d0[i][2 * f + 1] + b2s[n + 1]);
                        xo[n >> 1] = packh2(o0, o1);
                    }
                }
            }
        } else {
            #pragma unroll
            for (int f = 0; f < 2; f++) {
                int row = mbase + qr + f * 8;
                int node = tile * 128 + row;
                if (node < N_NODES) {
                    int gg = batch[node];
                    float* pp = g_pool + (size_t)gg * HID;
                    #pragma unroll
                    for (int i = 0; i < 4; i++) {
                        int n = nbase + i * 8 + qp * 2;
                        float o0 = elu_fast(d0[i][2 * f]     + b2s[n]);
                        float o1 = elu_fast(d0[i][2 * f + 1] + b2s[n + 1]);
                        red_add_v2(pp + n, o0, o1);
                    }
                }
            }
        }
        // loop-top wait_group + __syncthreads orders GEMM2 As2-reads vs next epi1 writes
    }
}

// ---------------- head ----------------
__global__ void k_head(const float* __restrict__ w1, const float* __restrict__ b1,
                       const float* __restrict__ w2, const float* __restrict__ b2,
                       float* __restrict__ out) {
    __shared__ float p_s[HID], h_s[HID];
    int g = blockIdx.x, t = threadIdx.x;
    p_s[t] = g_pool[g * HID + t];
    __syncthreads();
    float acc = b1[t];
    #pragma unroll 8
    for (int k = 0; k < HID; k++) acc += p_s[k] * w1[k * N_TASKS + t];
    h_s[t] = fmaxf(acc, 0.f);
    __syncthreads();
    acc = b2[t];
    #pragma unroll 8
    for (int k = 0; k < HID; k++) acc += h_s[k] * w2[k * N_TASKS + t];
    out[g * N_TASKS + t] = acc;
}

// ---------------- launch ----------------
extern "C" void kernel_launch(void* const* d_in, const int* in_sizes, int n_in,
                              void* d_out, int out_size) {
    const int*   x_idx    = (const int*)  d_in[0];
    const int*   ei       = (const int*)  d_in[1];
    const int*   ea       = (const int*)  d_in[2];
    const int*   batch    = (const int*)  d_in[3];
    const float* atom_emb = (const float*)d_in[4];
    const float* bond_emb = (const float*)d_in[5];
    const float* we0      = (const float*)d_in[6];
    const float* be0      = (const float*)d_in[7];
    const float* w1_0     = (const float*)d_in[8];
    const float* b1_0     = (const float*)d_in[9];
    const float* w2_0     = (const float*)d_in[10];
    const float* b2_0     = (const float*)d_in[11];
    const float* we1      = (const float*)d_in[12];
    const float* be1      = (const float*)d_in[13];
    const float* w1_1     = (const float*)d_in[14];
    const float* b1_1     = (const float*)d_in[15];
    const float* w2_1     = (const float*)d_in[16];
    const float* b2_1     = (const float*)d_in[17];
    const float* lin1_w   = (const float*)d_in[18];
    const float* lin1_b   = (const float*)d_in[19];
    const float* lin2_w   = (const float*)d_in[20];
    const float* lin2_b   = (const float*)d_in[21];
    float* out = (float*)d_out;

    // smem: W1 + W2 + As + As2 + biases
    int smem0 = 16384 + 32768 + 16384 + 32768 + 1024;   //  99328
    int smem1 = 32768 + 32768 + 32768 + 32768 + 1024;   // 132096
    cudaFuncSetAttribute(k_mlp_cp<64, false>, cudaFuncAttributeMaxDynamicSharedMemorySize, smem0);
    cudaFuncSetAttribute(k_mlp_cp<128, true>, cudaFuncAttributeMaxDynamicSharedMemorySize, smem1);

    k_prep   <<<2048, 256>>>(bond_emb, we0, be0, we1, be1, w1_0, w2_0, w1_1, w2_1, x_idx, atom_emb);
    k_hist   <<<1480, 256>>>(ei);
    k_scan1  <<<NB_SCAN, 1024>>>();
    k_scan2  <<<NB_SCAN, 1024>>>();
    k_scatter<<<1480, 256>>>(ei, ea);
    k_agg0   <<<1480, 256>>>();
    k_mlp_cp<64, false><<<148, 1024, smem0>>>(b1_0, b2_0, batch);
    k_agg1   <<<1480, 256>>>();
    k_mlp_cp<128, true><<<148, 1024, smem1>>>(b1_1, b2_1, batch);
    k_head   <<<512, 128>>>(lin1_w, lin1_b, lin2_w, lin2_b, out);
}

// round 13
// speedup vs baseline: 1.0392x; 1.0392x over previous
#include <cuda_runtime.h>
#include <cuda_bf16.h>
#include <cuda_fp16.h>
#include <cstdint>

#define N_NODES 100000
#define N_EDGES 1600000
#define EMB 64
#define HID 128
#define N_GRAPHS 512
#define N_TASKS 128
#define FULLMASK 0xffffffffu
#define SLOT 64   // fixed slot capacity per node (Poisson(16) degrees; overflow -> g_ovf)

// ---------------- device scratch (static, no allocation) ----------------
__device__ __align__(16) uint4 g_x0h[N_NODES * 8];     // 64 halves per node
__device__ __align__(16) uint4 g_agg0h[N_NODES * 8];   // = x0 + sum(msg) after agg0
__device__ __align__(16) uint4 g_x1h[N_NODES * 16];    // 128 halves per node
__device__ __align__(16) uint4 g_agg1h[N_NODES * 16];  // = x1 + sum(msg) after agg1
__device__ __align__(16) uint4 g_t0h[16 * 8];          // bond table L0 (fp16)
__device__ __align__(16) uint4 g_t1h[16 * 16];         // bond table L1 (fp16)
__device__ __align__(16) float g_pool[N_GRAPHS * HID];
// fp16 weights, pre-swizzled: layer0 [W1 16384 | W2 32768], layer1 [W1 32768 | W2 32768]
__device__ __align__(16) unsigned char g_wb0[49152];
__device__ __align__(16) unsigned char g_wb1[65536];
// slot-array "CSR without the scan" (built once, shared by both layers)
__device__ int g_cnt[N_NODES];
__device__ uint32_t g_slots[N_NODES * SLOT];   // src | (bt << 17)
__device__ uint2 g_ovf[N_EDGES];               // {rec, dst} — pathological overflow only
__device__ int g_novf;

// ---------------- helpers ----------------
__device__ __forceinline__ void red_add_v2(float* p, float a, float b) {
    asm volatile("red.global.add.v2.f32 [%0], {%1,%2};"
                 :: "l"(p), "f"(a), "f"(b) : "memory");
}
__device__ __forceinline__ void cp16(uint32_t dst, const void* src, bool valid) {
    if (valid)
        asm volatile("cp.async.cg.shared.global [%0], [%1], 16;" :: "r"(dst), "l"(src) : "memory");
    else
        asm volatile("cp.async.cg.shared.global [%0], [%1], 16, 0;" :: "r"(dst), "l"(src) : "memory");
}
__device__ __forceinline__ float elu_fast(float x) { return x > 0.f ? x : (__expf(x) - 1.f); }
__device__ __forceinline__ uint32_t smem_u32(const void* p) {
    uint32_t a;
    asm("{ .reg .u64 t; cvta.to.shared.u64 t, %1; cvt.u32.u64 %0, t; }" : "=r"(a) : "l"(p));
    return a;
}
// half2 relu(a+b)
__device__ __forceinline__ uint32_t h2ra(uint32_t a, uint32_t b) {
    __half2 s = __hadd2(*(__half2*)&a, *(__half2*)&b);
    __half2 z = __float2half2_rn(0.f);
    s = __hmax2(s, z);
    return *(uint32_t*)&s;
}
__device__ __forceinline__ uint32_t h2a(uint32_t a, uint32_t b) {
    __half2 s = __hadd2(*(__half2*)&a, *(__half2*)&b);
    return *(uint32_t*)&s;
}
__device__ __forceinline__ uint4 msg4(uint4 v, uint4 t) {
    uint4 m;
    m.x = h2ra(v.x, t.x); m.y = h2ra(v.y, t.y);
    m.z = h2ra(v.z, t.z); m.w = h2ra(v.w, t.w);
    return m;
}
__device__ __forceinline__ uint4 hadd2x4(uint4 a, uint4 b) {
    uint4 o;
    o.x = h2a(a.x, b.x); o.y = h2a(a.y, b.y);
    o.z = h2a(a.z, b.z); o.w = h2a(a.w, b.w);
    return o;
}
__device__ __forceinline__ uint4 shfl_xor4(uint4 a, int m) {
    uint4 o;
    o.x = __shfl_xor_sync(FULLMASK, a.x, m);
    o.y = __shfl_xor_sync(FULLMASK, a.y, m);
    o.z = __shfl_xor_sync(FULLMASK, a.z, m);
    o.w = __shfl_xor_sync(FULLMASK, a.w, m);
    return o;
}
__device__ __forceinline__ uint32_t packh2(float a, float b) {
    __half2 h = __floats2half2_rn(a, b);
    return *(uint32_t*)&h;
}
// swizzled byte offset within a [row][col] 16-bit-element tile; rowb bytes per row.
__device__ __forceinline__ uint32_t swz(int r, int c, int rowb) {
    return (uint32_t)(r * rowb + ((((c >> 3) ^ (r & 7))) << 4) + (c & 7) * 2);
}
__device__ __forceinline__ void ldsm_x4(uint32_t a[4], uint32_t addr) {
    asm volatile("ldmatrix.sync.aligned.m8n8.x4.shared.b16 {%0,%1,%2,%3}, [%4];"
                 : "=r"(a[0]), "=r"(a[1]), "=r"(a[2]), "=r"(a[3]) : "r"(addr));
}
__device__ __forceinline__ void ldsm_x4_t(uint32_t a[4], uint32_t addr) {
    asm volatile("ldmatrix.sync.aligned.m8n8.x4.trans.shared.b16 {%0,%1,%2,%3}, [%4];"
                 : "=r"(a[0]), "=r"(a[1]), "=r"(a[2]), "=r"(a[3]) : "r"(addr));
}
__device__ __forceinline__ void mma_fp16(float d[4], const uint32_t a[4], uint32_t b0, uint32_t b1) {
    asm volatile("mma.sync.aligned.m16n8k16.row.col.f32.f16.f16.f32 "
                 "{%0,%1,%2,%3}, {%4,%5,%6,%7}, {%8,%9}, {%0,%1,%2,%3};"
                 : "+f"(d[0]), "+f"(d[1]), "+f"(d[2]), "+f"(d[3])
                 : "r"(a[0]), "r"(a[1]), "r"(a[2]), "r"(a[3]), "r"(b0), "r"(b1));
}

// ---------------- prep: zeros + fp16 bond tables + weight blobs + gather ----
__global__ void k_prep(const float* __restrict__ bond_emb,
                       const float* __restrict__ we0, const float* __restrict__ be0,
                       const float* __restrict__ we1, const float* __restrict__ be1,
                       const float* __restrict__ w1_0, const float* __restrict__ w2_0,
                       const float* __restrict__ w1_1, const float* __restrict__ w2_1,
                       const int* __restrict__ x_idx, const float* __restrict__ atom_emb) {
    int tid = blockIdx.x * blockDim.x + threadIdx.x;
    int nth = gridDim.x * blockDim.x;
    if (tid == 0) g_novf = 0;
    for (int i = tid; i < N_GRAPHS * HID; i += nth) g_pool[i] = 0.f;
    for (int i = tid; i < N_NODES; i += nth) g_cnt[i] = 0;
    for (int i = tid; i < 16 * EMB; i += nth) {
        int bt = i >> 6, o = i & 63;
        float acc = be0[o];
        #pragma unroll 8
        for (int k = 0; k < EMB; k++) acc += bond_emb[bt * EMB + k] * we0[k * EMB + o];
        ((__half*)g_t0h)[i] = __float2half_rn(acc);
    }
    for (int i = tid; i < 16 * HID; i += nth) {
        int bt = i >> 7, o = i & 127;
        float acc = be1[o];
        #pragma unroll 8
        for (int k = 0; k < EMB; k++) acc += bond_emb[bt * EMB + k] * we1[k * HID + o];
        ((__half*)g_t1h)[i] = __float2half_rn(acc);
    }
    for (int i = tid; i < 64 * 128; i += nth) {          // L0 W1
        int k = i >> 7, n = i & 127;
        *(__half*)(g_wb0 + swz(k, n, 256)) = __float2half_rn(w1_0[i]);
    }
    for (int i = tid; i < 128 * 128; i += nth) {         // L0 W2
        int k = i >> 7, n = i & 127;
        *(__half*)(g_wb0 + 16384 + swz(k, n, 256)) = __float2half_rn(w2_0[i]);
    }
    for (int i = tid; i < 128 * 128; i += nth) {         // L1 W1
        int k = i >> 7, n = i & 127;
        *(__half*)(g_wb1 + swz(k, n, 256)) = __float2half_rn(w1_1[i]);
    }
    for (int i = tid; i < 128 * 128; i += nth) {         // L1 W2
        int k = i >> 7, n = i & 127;
        *(__half*)(g_wb1 + 32768 + swz(k, n, 256)) = __float2half_rn(w2_1[i]);
    }
    // gather atom embeddings (fp32 -> fp16)
    const float4* ae = (const float4*)atom_emb;
    uint2* x0 = (uint2*)g_x0h;
    const int NITEMS = N_NODES * 16;
    for (int i = tid; i < NITEMS; i += nth) {
        int node = i >> 4;
        int c = i & 15;
        int a = x_idx[node];
        float4 v = ae[a * 16 + c];
        uint2 o;
        o.x = packh2(v.x, v.y); o.y = packh2(v.z, v.w);
        x0[i] = o;
    }
}

// ---------------- slot scatter: one pass, no hist/scan ----------------
__global__ void k_scatter(const int* __restrict__ ei, const int* __restrict__ ea) {
    int tid = blockIdx.x * blockDim.x + threadIdx.x;
    int nth = gridDim.x * blockDim.x;
    for (int e = tid; e < N_EDGES; e += nth) {
        int d = ei[N_EDGES + e];
        uint32_t rec = (uint32_t)ei[e] | ((uint32_t)ea[e] << 17);
        int pos = atomicAdd(&g_cnt[d], 1);
        if (pos < SLOT) {
            g_slots[d * SLOT + pos] = rec;
        } else {
            int o = atomicAdd(&g_novf, 1);
            g_ovf[o] = make_uint2(rec, (uint32_t)d);
        }
    }
}

// ---------------- agg layer 0: warp per node, 4 edge-slots x 8 chunks ----------------
__global__ void k_agg0() {
    __shared__ uint4 t0s[16 * 8];
    for (int i = threadIdx.x; i < 16 * 8; i += blockDim.x) t0s[i] = g_t0h[i];
    __syncthreads();
    int lane = threadIdx.x & 31;
    int wid = (blockIdx.x * blockDim.x + threadIdx.x) >> 5;
    int nw = (gridDim.x * blockDim.x) >> 5;
    int e = lane >> 3, c = lane & 7;
    int novf = g_novf;
    for (int n = wid; n < N_NODES; n += nw) {
        int cn = g_cnt[n];
        int deg = min(cn, SLOT);
        uint4 acc = (e == 0) ? g_x0h[n * 8 + c] : make_uint4(0u, 0u, 0u, 0u);  // pre-bias x
        const uint32_t* sl = g_slots + n * SLOT;
        for (int base = 0; base < deg; base += 32) {
            int nrec = min(32, deg - base);
            uint32_t rec = 0u;
            if (base + lane < deg) rec = sl[base + lane];
            #pragma unroll 4
            for (int j = 0; j < nrec; j += 4) {
                int idx = j + e;
                uint32_t r = __shfl_sync(FULLMASK, rec, idx & 31);
                if (idx < nrec) {
                    int src = r & 0x1FFFF;
                    int bt  = r >> 17;
                    uint4 v = g_x0h[src * 8 + c];
                    uint4 t = t0s[bt * 8 + c];
                    acc = hadd2x4(acc, msg4(v, t));
                }
            }
        }
        if (cn > SLOT) {   // pathological overflow: owning warp drains matching entries
            for (int i = 0; i < novf; i++) {
                uint2 od = g_ovf[i];
                if ((int)od.y == n && e == 0) {
                    int src = od.x & 0x1FFFF;
                    int bt  = od.x >> 17;
                    acc = hadd2x4(acc, msg4(g_x0h[src * 8 + c], t0s[bt * 8 + c]));
                }
            }
        }
        acc = hadd2x4(acc, shfl_xor4(acc, 8));
        acc = hadd2x4(acc, shfl_xor4(acc, 16));
        if (lane < 8) g_agg0h[n * 8 + c] = acc;
    }
}

// ---------------- agg layer 1: warp per node, 2 edge-slots x 16 chunks ----------------
__global__ void k_agg1() {
    __shared__ uint4 t1s[16 * 16];
    for (int i = threadIdx.x; i < 16 * 16; i += blockDim.x) t1s[i] = g_t1h[i];
    __syncthreads();
    int lane = threadIdx.x & 31;
    int wid = (blockIdx.x * blockDim.x + threadIdx.x) >> 5;
    int nw = (gridDim.x * blockDim.x) >> 5;
    int e = lane >> 4, c = lane & 15;
    int novf = g_novf;
    for (int n = wid; n < N_NODES; n += nw) {
        int cn = g_cnt[n];
        int deg = min(cn, SLOT);
        uint4 acc = (e == 0) ? g_x1h[n * 16 + c] : make_uint4(0u, 0u, 0u, 0u); // pre-bias x
        const uint32_t* sl = g_slots + n * SLOT;
        for (int base = 0; base < deg; base += 32) {
            int nrec = min(32, deg - base);
            uint32_t rec = 0u;
            if (base + lane < deg) rec = sl[base + lane];
            #pragma unroll 4
            for (int j = 0; j < nrec; j += 2) {
                int idx = j + e;
                uint32_t r = __shfl_sync(FULLMASK, rec, idx & 31);
                if (idx < nrec) {
                    int src = r & 0x1FFFF;
                    int bt  = r >> 17;
                    uint4 v = g_x1h[src * 16 + c];
                    uint4 t = t1s[bt * 16 + c];
                    acc = hadd2x4(acc, msg4(v, t));
                }
            }
        }
        if (cn > SLOT) {   // pathological overflow
            for (int i = 0; i < novf; i++) {
                uint2 od = g_ovf[i];
                if ((int)od.y == n && e == 0) {
                    int src = od.x & 0x1FFFF;
                    int bt  = od.x >> 17;
                    acc = hadd2x4(acc, msg4(g_x1h[src * 16 + c], t1s[bt * 16 + c]));
                }
            }
        }
        acc = hadd2x4(acc, shfl_xor4(acc, 16));
        if (lane < 16) g_agg1h[n * 16 + c] = acc;
    }
}

// ============ GINE MLP: cp.async-pipelined HMMA fp16 (R11-proven) ============
template<int K1, bool L1>
__global__ void __launch_bounds__(1024, 1)
k_mlp_cp(const float* __restrict__ b1, const float* __restrict__ b2,
         const int* __restrict__ batch) {
    extern __shared__ char smem[];
    constexpr int W1B = K1 * 256;
    constexpr int W2B = 32768;
    constexpr int RB  = K1 * 2;            // bytes per As row
    constexpr int ASB = 128 * RB;
    constexpr int CPR = RB / 16;           // 16B chunks per row (8 or 16)
    char* W1s  = smem;
    char* W2s  = smem + W1B;
    char* Asb  = smem + W1B + W2B;
    char* As2b = Asb + ASB;
    float* b1s = (float*)(As2b + 32768);
    float* b2s = b1s + 128;

    const char* ag = (const char*)(L1 ? g_agg1h : g_agg0h);
    const unsigned char* blob = L1 ? g_wb1 : g_wb0;

    int tid = threadIdx.x;
    {
        const uint4* src = (const uint4*)blob;
        uint4* dst = (uint4*)smem;
        for (int i = tid; i < (W1B + W2B) / 16; i += 1024) dst[i] = src[i];
    }
    if (tid < 128) { b1s[tid] = b1[tid]; b2s[tid] = b2[tid]; }

    uint32_t As_u  = smem_u32(Asb);
    uint32_t As2_u = smem_u32(As2b);
    uint32_t W1_u  = smem_u32(W1s);
    uint32_t W2_u  = smem_u32(W2s);

    int lane = tid & 31, wq = tid >> 5;
    int mbase = (wq & 7) * 16;
    int nbase = (wq >> 3) * 32;
    int g = lane >> 3, lr = lane & 7;
    int fr = (g & 1) * 8 + lr;
    int fc8 = (g >> 1) * 8;
    int qr = lane >> 2, qp = lane & 3;

    const int NT = (N_NODES + 127) / 128;  // 782

    auto prefetch = [&](int T) {
        #pragma unroll
        for (int v = 0; v < (128 * CPR) / 1024; v++) {
            int idx = v * 1024 + tid;
            int r = idx / CPR, c = idx % CPR;
            int node = T * 128 + r;
            uint32_t dst = As_u + r * RB + (uint32_t)((c ^ (r & 7)) << 4);
            bool valid = node < N_NODES;
            const char* src = valid ? ag + ((size_t)node * RB + c * 16) : ag;
            cp16(dst, src, valid);
        }
        asm volatile("cp.async.commit_group;" ::: "memory");
    };

    if ((int)blockIdx.x < NT) prefetch(blockIdx.x);

    for (int tile = blockIdx.x; tile < NT; tile += gridDim.x) {
        asm volatile("cp.async.wait_group 0;" ::: "memory");
        __syncthreads();   // As (and first-pass weights) visible to all

        float d0[4][4];
        #pragma unroll
        for (int i = 0; i < 4; i++)
            #pragma unroll
            for (int j = 0; j < 4; j++) d0[i][j] = 0.f;

        // ---- GEMM1: A[128xK1] @ W1 ----
        #pragma unroll
        for (int ks = 0; ks < K1 / 16; ks++) {
            uint32_t a0[4];
            ldsm_x4(a0, As_u + swz(mbase + fr, ks * 16 + fc8, RB));
            #pragma unroll
            for (int np = 0; np < 2; np++) {
                uint32_t bh[4];
                ldsm_x4_t(bh, W1_u + swz(ks * 16 + fr, nbase + np * 16 + fc8, 256));
                mma_fp16(d0[2 * np], a0, bh[0], bh[1]);
                mma_fp16(d0[2 * np + 1], a0, bh[2], bh[3]);
            }
        }

        // ---- epilogue1: t = elu(D + b1) -> As2 (fp16, swizzled) ----
        #pragma unroll
        for (int i = 0; i < 4; i++) {
            int n = nbase + i * 8 + qp * 2;
            float bb0 = b1s[n], bb1 = b1s[n + 1];
            *(uint32_t*)(As2b + swz(mbase + qr,     n, 256)) = packh2(elu_fast(d0[i][0] + bb0), elu_fast(d0[i][1] + bb1));
            *(uint32_t*)(As2b + swz(mbase + qr + 8, n, 256)) = packh2(elu_fast(d0[i][2] + bb0), elu_fast(d0[i][3] + bb1));
        }
        __syncthreads();   // As2 ready; all GEMM1 reads of As done

        // ---- prefetch next tile into As (overlaps GEMM2 + epilogue2) ----
        int nxt = tile + gridDim.x;
        if (nxt < NT) prefetch(nxt);

        #pragma unroll
        for (int i = 0; i < 4; i++)
            #pragma unroll
            for (int j = 0; j < 4; j++) d0[i][j] = 0.f;

        // ---- GEMM2: t[128x128] @ W2 ----
        #pragma unroll
        for (int ks = 0; ks < 8; ks++) {
            uint32_t a0[4];
            ldsm_x4(a0, As2_u + swz(mbase + fr, ks * 16 + fc8, 256));
            #pragma unroll
            for (int np = 0; np < 2; np++) {
                uint32_t bh[4];
                ldsm_x4_t(bh, W2_u + swz(ks * 16 + fr, nbase + np * 16 + fc8, 256));
                mma_fp16(d0[2 * np], a0, bh[0], bh[1]);
                mma_fp16(d0[2 * np + 1], a0, bh[2], bh[3]);
            }
        }

        // ---- epilogue2 ----
        if constexpr (!L1) {
            #pragma unroll
            for (int f = 0; f < 2; f++) {
                int row = mbase + qr + f * 8;
                int node = tile * 128 + row;
                if (node < N_NODES) {
                    uint32_t* xo = (uint32_t*)g_x1h + (size_t)node * 64;
                    #pragma unroll
                    for (int i = 0; i < 4; i++) {
                        int n = nbase + i * 8 + qp * 2;
                        float o0 = elu_fast(d0[i][2 * f]     + b2s[n]);
                        float o1 = elu_fast(d0[i][2 * f + 1] + b2s[n + 1]);
                        xo[n >> 1] = packh2(o0, o1);
                    }
                }
            }
        } else {
            #pragma unroll
            for (int f = 0; f < 2; f++) {
                int row = mbase + qr + f * 8;
                int node = tile * 128 + row;
                if (node < N_NODES) {
                    int gg = batch[node];
                    float* pp = g_pool + (size_t)gg * HID;
                    #pragma unroll
                    for (int i = 0; i < 4; i++) {
                        int n = nbase + i * 8 + qp * 2;
                        float o0 = elu_fast(d0[i][2 * f]     + b2s[n]);
                        float o1 = elu_fast(d0[i][2 * f + 1] + b2s[n + 1]);
                        red_add_v2(pp + n, o0, o1);
                    }
                }
            }
        }
        // loop-top wait_group + __syncthreads orders GEMM2 As2-reads vs next epi1 writes
    }
}

// ---------------- head ----------------
__global__ void k_head(const float* __restrict__ w1, const float* __restrict__ b1,
                       const float* __restrict__ w2, const float* __restrict__ b2,
                       float* __restrict__ out) {
    __shared__ float p_s[HID], h_s[HID];
    int g = blockIdx.x, t = threadIdx.x;
    p_s[t] = g_pool[g * HID + t];
    __syncthreads();
    float acc = b1[t];
    #pragma unroll 8
    for (int k = 0; k < HID; k++) acc += p_s[k] * w1[k * N_TASKS + t];
    h_s[t] = fmaxf(acc, 0.f);
    __syncthreads();
    acc = b2[t];
    #pragma unroll 8
    for (int k = 0; k < HID; k++) acc += h_s[k] * w2[k * N_TASKS + t];
    out[g * N_TASKS + t] = acc;
}

// ---------------- launch ----------------
extern "C" void kernel_launch(void* const* d_in, const int* in_sizes, int n_in,
                              void* d_out, int out_size) {
    const int*   x_idx    = (const int*)  d_in[0];
    const int*   ei       = (const int*)  d_in[1];
    const int*   ea       = (const int*)  d_in[2];
    const int*   batch    = (const int*)  d_in[3];
    const float* atom_emb = (const float*)d_in[4];
    const float* bond_emb = (const float*)d_in[5];
    const float* we0      = (const float*)d_in[6];
    const float* be0      = (const float*)d_in[7];
    const float* w1_0     = (const float*)d_in[8];
    const float* b1_0     = (const float*)d_in[9];
    const float* w2_0     = (const float*)d_in[10];
    const float* b2_0     = (const float*)d_in[11];
    const float* we1      = (const float*)d_in[12];
    const float* be1      = (const float*)d_in[13];
    const float* w1_1     = (const float*)d_in[14];
    const float* b1_1     = (const float*)d_in[15];
    const float* w2_1     = (const float*)d_in[16];
    const float* b2_1     = (const float*)d_in[17];
    const float* lin1_w   = (const float*)d_in[18];
    const float* lin1_b   = (const float*)d_in[19];
    const float* lin2_w   = (const float*)d_in[20];
    const float* lin2_b   = (const float*)d_in[21];
    float* out = (float*)d_out;

    // smem: W1 + W2 + As + As2 + biases
    int smem0 = 16384 + 32768 + 16384 + 32768 + 1024;   //  99328
    int smem1 = 32768 + 32768 + 32768 + 32768 + 1024;   // 132096
    cudaFuncSetAttribute(k_mlp_cp<64, false>, cudaFuncAttributeMaxDynamicSharedMemorySize, smem0);
    cudaFuncSetAttribute(k_mlp_cp<128, true>, cudaFuncAttributeMaxDynamicSharedMemorySize, smem1);

    k_prep   <<<2048, 256>>>(bond_emb, we0, be0, we1, be1, w1_0, w2_0, w1_1, w2_1, x_idx, atom_emb);
    k_scatter<<<1480, 256>>>(ei, ea);
    k_agg0   <<<1480, 256>>>();
    k_mlp_cp<64, false><<<148, 1024, smem0>>>(b1_0, b2_0, batch);
    k_agg1   <<<1480, 256>>>();
    k_mlp_cp<128, true><<<148, 1024, smem1>>>(b1_1, b2_1, batch);
    k_head   <<<512, 128>>>(lin1_w, lin1_b, lin2_w, lin2_b, out);
}